// round 8
// baseline (speedup 1.0000x reference)
#include <cuda_runtime.h>
#include <cuda_fp16.h>

#define VOCAB   50257
#define DIM     128
#define BATCH   32
#define M_SLOTS 512
#define S_TOK   6
#define T_TREE  128
#define L_TOK   64
#define SLOTS   (M_SLOTS + T_TREE)   // 640

#define SPLITS   20
#define SLOTS_PB (SLOTS / SPLITS)    // 32 slots per hop block
#define REC      132                 // m, s, pad, pad, o[128]
#define GBLK_PER_TAB (BATCH * SLOTS / 8)   // 2560
#define U1_BLOCKS    (SLOTS / 8)           // 80 table-1 blocks per batch
#define CN  ((size_t)3 * VOCAB * DIM)      // floats in tables 1..3

// fp16 copy of tables 1..3 (38.6 MB), fp16 slot memories (15.7 MB)
__device__ __align__(16) __half g_Ch[CN];
__device__ __align__(16) __half g_Mh[(size_t)3 * BATCH * SLOTS * DIM];
__device__ __align__(16) float  g_part[(size_t)2 * BATCH * SPLITS * REC];
__device__ __align__(16) float  g_u[2 * BATCH * DIM];   // [0]=u1, [1]=u2
__device__ int g_cnt[3 * BATCH];   // [0..31] hop1, [32..63] hop2, [64..95] u1

__device__ __forceinline__ float warp_max(float v) {
    #pragma unroll
    for (int o = 16; o; o >>= 1) v = fmaxf(v, __shfl_xor_sync(0xffffffffu, v, o));
    return v;
}
__device__ __forceinline__ float warp_sum(float v) {
    #pragma unroll
    for (int o = 16; o; o >>= 1) v += __shfl_xor_sync(0xffffffffu, v, o);
    return v;
}
__device__ __forceinline__ void acc_u2(float4& a, uint2 v) {
    float2 f0 = __half22float2(*reinterpret_cast<__half2*>(&v.x));
    float2 f1 = __half22float2(*reinterpret_cast<__half2*>(&v.y));
    a.x += f0.x; a.y += f0.y; a.z += f1.x; a.w += f1.y;
}

// ---------------------------------------------------------------------------
// K1: convert C tables 1..3 to fp16. Pure streaming; 8 floats per thread.
// ---------------------------------------------------------------------------
__global__ void __launch_bounds__(256) convert_kernel(const float* __restrict__ C)
{
    const size_t i = ((size_t)blockIdx.x * 256 + threadIdx.x) * 8;
    if (i >= CN) return;
    const float4* src = reinterpret_cast<const float4*>(C + (size_t)VOCAB * DIM + i);
    float4 a = src[0], b = src[1];
    union { __half2 h[4]; uint4 u; } cv;
    cv.h[0] = __floats2half2_rn(a.x, a.y);
    cv.h[1] = __floats2half2_rn(a.z, a.w);
    cv.h[2] = __floats2half2_rn(b.x, b.y);
    cv.h[3] = __floats2half2_rn(b.z, b.w);
    *reinterpret_cast<uint4*>(g_Ch + i) = cv.u;
}

// ---------------------------------------------------------------------------
// K2: gather-sum tables in REVERSE order (3,2,1) so hop-1's inputs (M1, M2)
// are the last writes and stay L2-resident. Warp per (tab,b,slot).
// Last table-1 block per batch computes u1[b] = mean slot memory (hop 0).
// ---------------------------------------------------------------------------
__global__ void __launch_bounds__(256) gather_kernel(
    const int* __restrict__ story, const int* __restrict__ kb)
{
    const int lane = threadIdx.x & 31;
    const int wg   = blockIdx.x * 8 + (threadIdx.x >> 5);
    const int tpos = wg / (BATCH * SLOTS);           // processing position 0..2
    const int tab  = 2 - tpos;                       // table index: 2,1,0
    const int rem  = wg % (BATCH * SLOTS);
    const int b    = rem / SLOTS;
    const int slot = rem % SLOTS;

    const __half* __restrict__ Ct = g_Ch + (size_t)tab * VOCAB * DIM;
    float4 acc = make_float4(0.f, 0.f, 0.f, 0.f);

    if (slot < M_SLOTS) {
        const int* toks = story + ((size_t)b * M_SLOTS + slot) * S_TOK;
        int tk[S_TOK];
        #pragma unroll
        for (int j = 0; j < S_TOK; ++j) tk[j] = toks[j];
        #pragma unroll
        for (int j = 0; j < S_TOK; ++j) {
            uint2 v = reinterpret_cast<const uint2*>(Ct + (size_t)tk[j] * DIM)[lane];
            acc_u2(acc, v);
        }
    } else {
        const int* toks = kb + ((size_t)b * T_TREE + (slot - M_SLOTS)) * L_TOK;
        float4 a0 = make_float4(0.f, 0.f, 0.f, 0.f);
        float4 a1 = a0, a2 = a0, a3 = a0;
        #pragma unroll 4
        for (int j = 0; j < L_TOK; j += 4) {
            int t0 = toks[j + 0], t1 = toks[j + 1];
            int t2 = toks[j + 2], t3 = toks[j + 3];
            uint2 v0 = reinterpret_cast<const uint2*>(Ct + (size_t)t0 * DIM)[lane];
            uint2 v1 = reinterpret_cast<const uint2*>(Ct + (size_t)t1 * DIM)[lane];
            uint2 v2 = reinterpret_cast<const uint2*>(Ct + (size_t)t2 * DIM)[lane];
            uint2 v3 = reinterpret_cast<const uint2*>(Ct + (size_t)t3 * DIM)[lane];
            acc_u2(a0, v0); acc_u2(a1, v1); acc_u2(a2, v2); acc_u2(a3, v3);
        }
        acc.x = (a0.x + a1.x) + (a2.x + a3.x);
        acc.y = (a0.y + a1.y) + (a2.y + a3.y);
        acc.z = (a0.z + a1.z) + (a2.z + a3.z);
        acc.w = (a0.w + a1.w) + (a2.w + a3.w);
    }

    union { __half2 h[2]; uint2 u; } st;
    st.h[0] = __floats2half2_rn(acc.x, acc.y);
    st.h[1] = __floats2half2_rn(acc.z, acc.w);
    reinterpret_cast<uint2*>(g_Mh + ((size_t)tab * BATCH * SLOTS + rem) * DIM)[lane] = st.u;

    // ---- last table-1 (tab==0) block for this batch computes u1[b] ----
    if (tab == 0) {
        __threadfence();
        __syncthreads();
        __shared__ int s_old;
        if (threadIdx.x == 0)
            s_old = atomicAdd(&g_cnt[2 * BATCH + b], 1);
        __syncthreads();
        if (s_old == U1_BLOCKS - 1) {
            const int d2  = threadIdx.x & 63;    // half2 index (dims 2*d2, 2*d2+1)
            const int grp = threadIdx.x >> 6;    // 0..3, 160 slots each
            const __half2* __restrict__ base =
                reinterpret_cast<const __half2*>(g_Mh + (size_t)b * SLOTS * DIM);
            float2 a = make_float2(0.f, 0.f);
            #pragma unroll 8
            for (int s = grp * 160; s < (grp + 1) * 160; ++s) {
                float2 v = __half22float2(base[(size_t)s * 64 + d2]);
                a.x += v.x; a.y += v.y;
            }
            __shared__ float2 sm[256];
            sm[threadIdx.x] = a;
            __syncthreads();
            if (grp == 0) {
                float2 tot = sm[d2];
                #pragma unroll
                for (int i = 1; i < 4; ++i) {
                    float2 p = sm[i * 64 + d2];
                    tot.x += p.x; tot.y += p.y;
                }
                g_u[b * DIM + 2 * d2]     = tot.x * (1.0f / SLOTS);
                g_u[b * DIM + 2 * d2 + 1] = tot.y * (1.0f / SLOTS);
            }
            if (threadIdx.x == 0) g_cnt[2 * BATCH + b] = 0;   // reset for replay
        }
    }
}

// ---------------------------------------------------------------------------
// One hop: block = (b, split) handles 32 slots. All key AND value rows are
// loaded up-front (8 independent loads/warp); values held in registers
// through the softmax. Last split-block combines 20 partials into dst[b].
// ---------------------------------------------------------------------------
__global__ void __launch_bounds__(256) hop_kernel(int kidx, int vidx,
                                                  int uidx, int pidx,
                                                  float* __restrict__ dst)
{
    const int b     = blockIdx.x / SPLITS;
    const int split = blockIdx.x % SPLITS;
    const int tid   = threadIdx.x;
    const int w     = tid >> 5;
    const int lane  = tid & 31;

    __shared__ float  s_score[SLOTS_PB];   // 32
    __shared__ float4 s_part[8][32];
    __shared__ float  s_ms[2];

    const float4 u4 =
        reinterpret_cast<const float4*>(g_u + (uidx * BATCH + b) * DIM)[lane];

    const __half* __restrict__ Mk =
        g_Mh + ((size_t)(kidx * BATCH + b) * SLOTS + split * SLOTS_PB) * DIM;
    const __half* __restrict__ Mv =
        g_Mh + ((size_t)(vidx * BATCH + b) * SLOTS + split * SLOTS_PB) * DIM;

    // issue all 8 loads (4 key rows + 4 value rows) before any compute
    uint2 kr[4], vr[4];
    #pragma unroll
    for (int k = 0; k < 4; ++k) {
        const int ls = w + k * 8;
        kr[k] = reinterpret_cast<const uint2*>(Mk + (size_t)ls * DIM)[lane];
        vr[k] = reinterpret_cast<const uint2*>(Mv + (size_t)ls * DIM)[lane];
    }

    // scores
    #pragma unroll
    for (int k = 0; k < 4; ++k) {
        float4 v = make_float4(0.f, 0.f, 0.f, 0.f);
        acc_u2(v, kr[k]);
        float p = v.x * u4.x + v.y * u4.y + v.z * u4.z + v.w * u4.w;
        p = warp_sum(p);
        if (lane == 0) s_score[w + k * 8] = p;
    }
    __syncthreads();

    // local softmax over 32 scores (warp 0, full warp)
    if (w == 0) {
        float sc = s_score[lane];
        float m  = warp_max(sc);
        float e  = __expf(sc - m);
        float s  = warp_sum(e);
        s_score[lane] = e;
        if (lane == 0) { s_ms[0] = m; s_ms[1] = s; }
    }
    __syncthreads();

    // weighted value partial from registers
    float4 o4 = make_float4(0.f, 0.f, 0.f, 0.f);
    #pragma unroll
    for (int k = 0; k < 4; ++k) {
        const float p = s_score[w + k * 8];
        float4 v = make_float4(0.f, 0.f, 0.f, 0.f);
        acc_u2(v, vr[k]);
        o4.x += p * v.x; o4.y += p * v.y; o4.z += p * v.z; o4.w += p * v.w;
    }
    s_part[w][lane] = o4;
    __syncthreads();

    if (w == 0) {
        float4 r = make_float4(0.f, 0.f, 0.f, 0.f);
        #pragma unroll
        for (int i = 0; i < 8; ++i) {
            float4 p = s_part[i][lane];
            r.x += p.x; r.y += p.y; r.z += p.z; r.w += p.w;
        }
        float* rec = g_part + ((size_t)(pidx * BATCH + b) * SPLITS + split) * REC;
        reinterpret_cast<float4*>(rec + 4)[lane] = r;
        if (lane == 0) { rec[0] = s_ms[0]; rec[1] = s_ms[1]; }
    }

    // ---- last-block combine ----
    __threadfence();
    __syncthreads();
    __shared__ int s_old;
    if (tid == 0)
        s_old = atomicAdd(&g_cnt[pidx * BATCH + b], 1);
    __syncthreads();
    if (s_old != SPLITS - 1) return;

    const float* __restrict__ base =
        g_part + ((size_t)(pidx * BATCH + b)) * SPLITS * REC;

    __shared__ float  c_s[8];
    __shared__ float4 c_o[8][32];

    // every warp computes the global max over 20 record maxima (L1 hits)
    float mi = (lane < SPLITS) ? __ldcg(base + (size_t)lane * REC) : -1e30f;
    const float m = warp_max(mi);

    // warp w accumulates records w, w+8, w+16 (if < 20)
    float  s_acc = 0.f;
    float4 o4c = make_float4(0.f, 0.f, 0.f, 0.f);
    #pragma unroll
    for (int r = w; r < SPLITS; r += 8) {
        const float* rec = base + (size_t)r * REC;
        float e = __expf(__ldcg(rec) - m);
        s_acc += __ldcg(rec + 1) * e;
        float4 oi = __ldcg(reinterpret_cast<const float4*>(rec + 4) + lane);
        o4c.x += e * oi.x; o4c.y += e * oi.y; o4c.z += e * oi.z; o4c.w += e * oi.w;
    }
    c_o[w][lane] = o4c;
    if (lane == 0) c_s[w] = s_acc;
    __syncthreads();

    if (w == 0) {
        float stot = 0.f;
        #pragma unroll
        for (int i = 0; i < 8; ++i) stot += c_s[i];
        float4 r = make_float4(0.f, 0.f, 0.f, 0.f);
        #pragma unroll
        for (int i = 0; i < 8; ++i) {
            float4 p = c_o[i][lane];
            r.x += p.x; r.y += p.y; r.z += p.z; r.w += p.w;
        }
        const float inv = 1.0f / stot;
        float4 res;
        res.x = u4.x + r.x * inv;
        res.y = u4.y + r.y * inv;
        res.z = u4.z + r.z * inv;
        res.w = u4.w + r.w * inv;
        reinterpret_cast<float4*>(dst + b * DIM)[lane] = res;
    }
    if (tid == 0) g_cnt[pidx * BATCH + b] = 0;   // reset for graph replay
}

// ---------------------------------------------------------------------------
extern "C" void kernel_launch(void* const* d_in, const int* in_sizes, int n_in,
                              void* d_out, int out_size)
{
    const float* C     = (const float*)d_in[0];  // [4, 50257, 128]
    const int*   story = (const int*)  d_in[1];  // [32, 512, 6]
    const int*   kb    = (const int*)  d_in[2];  // [32, 128, 64]
    float*       out   = (float*)d_out;          // [32, 128]

    float* u2;
    cudaGetSymbolAddress((void**)&u2, g_u);
    u2 += BATCH * DIM;

    const int cthreads = (int)(CN / 8);                      // 2,412,336
    convert_kernel<<<(cthreads + 255) / 256, 256>>>(C);      // fp32 -> fp16
    gather_kernel<<<3 * GBLK_PER_TAB, 256>>>(story, kb);     // tables 3,2,1 + u1
    hop_kernel<<<BATCH * SPLITS, 256>>>(0, 1, 0, 0, u2);     // hop1 -> u2
    hop_kernel<<<BATCH * SPLITS, 256>>>(1, 2, 1, 1, out);    // hop2 -> out
}